// round 6
// baseline (speedup 1.0000x reference)
#include <cuda_runtime.h>
#include <math.h>

#define NB 4
#define NC 128
#define NP 128
#define ND 128
#define NG 512
#define NROW (NB * NC * NP)            // 65536
#define NELEM ((size_t)NROW * ND)      // 8388608

typedef unsigned long long u64;

#define S130 130
#define S129 129

// -------------------- scratch --------------------
__device__ float g_qzn[NELEM];
__device__ float g_xacc[NELEM];
__device__ float g_tu[NELEM];
__device__ float g_tv[NELEM];
__device__ float g_cu[NELEM];
__device__ float g_cv[NELEM];

// -------------------- packed f32x2 helpers --------------------
__device__ __forceinline__ u64 pk2(float lo, float hi) {
    u64 r; asm("mov.b64 %0, {%1,%2};" : "=l"(r) : "f"(lo), "f"(hi)); return r;
}
__device__ __forceinline__ float2 up2(u64 v) {
    float2 f; asm("mov.b64 {%0,%1}, %2;" : "=f"(f.x), "=f"(f.y) : "l"(v)); return f;
}
__device__ __forceinline__ void fma2(u64 &d, u64 a, u64 b) {
    asm("fma.rn.f32x2 %0, %1, %2, %0;" : "+l"(d) : "l"(a), "l"(b));
}

// =====================================================================
// K1: qzn = LN(qz); xacc = 0.5*(qz + unary).  one warp per row.
// =====================================================================
__global__ __launch_bounds__(256) void k_ln_init(
    const float* __restrict__ qz, const float* __restrict__ unary,
    const float* __restrict__ gamma, const float* __restrict__ beta) {
    int row = blockIdx.x * 8 + (threadIdx.x >> 5);
    int lane = threadIdx.x & 31;
    size_t base = (size_t)row * 128 + lane * 4;
    float4 v = *(const float4*)(qz + base);
    float s = v.x + v.y + v.z + v.w;
    float ss = v.x * v.x + v.y * v.y + v.z * v.z + v.w * v.w;
#pragma unroll
    for (int o = 16; o > 0; o >>= 1) {
        s += __shfl_xor_sync(0xffffffffu, s, o);
        ss += __shfl_xor_sync(0xffffffffu, ss, o);
    }
    float m = s * (1.0f / 128.0f);
    float var = ss * (1.0f / 128.0f) - m * m;
    float inv = rsqrtf(var + 1e-5f);
    float4 u = *(const float4*)(unary + base);
    float4 g4 = *(const float4*)(gamma + lane * 4);
    float4 b4 = *(const float4*)(beta + lane * 4);
    float4 qn, xa;
    qn.x = (v.x - m) * inv * g4.x + b4.x;
    qn.y = (v.y - m) * inv * g4.y + b4.y;
    qn.z = (v.z - m) * inv * g4.z + b4.z;
    qn.w = (v.w - m) * inv * g4.w + b4.w;
    xa.x = 0.5f * (v.x + u.x);
    xa.y = 0.5f * (v.y + u.y);
    xa.z = 0.5f * (v.z + u.z);
    xa.w = 0.5f * (v.w + u.w);
    *(float4*)(g_qzn + base) = qn;
    *(float4*)(g_xacc + base) = xa;
}

// =====================================================================
// K2: 4 batched linears. 128 rows/block, 512 threads, R=4 (8 rows/warp).
// Xt: k-major [128k][130r] broadcast; Ws: [128o][129k].
// =====================================================================
__global__ __launch_bounds__(512) void k_gemm4(
    const float* __restrict__ w0, const float* __restrict__ w1,
    const float* __restrict__ w2, const float* __restrict__ w3) {
    extern __shared__ float sm[];
    float* Xt = sm;                 // 128 x 130
    float* Ws = sm + 128 * S130;    // 128 x 129
    int tid = threadIdx.x, lane = tid & 31, w = tid >> 5;
    int row0 = blockIdx.x * 128;
    int b = row0 >> 14;
    int which = blockIdx.y;
    const float* W = (which == 0 ? w0 : which == 1 ? w1 : which == 2 ? w2 : w3)
                     + (size_t)b * 16384;
    float* O = (which == 0 ? g_tu : which == 1 ? g_tv : which == 2 ? g_cu : g_cv);

    for (int i = tid; i < 16384; i += 512) {
        int r = i >> 7, k = i & 127;
        Xt[k * S130 + r] = g_qzn[(size_t)(row0 + r) * 128 + k];
        Ws[r * S129 + k] = W[i];
    }
    __syncthreads();

    u64 acc[4][4];
#pragma unroll
    for (int i = 0; i < 4; i++)
#pragma unroll
        for (int j = 0; j < 4; j++) acc[i][j] = 0ull;

    int rbase = w * 8;
#pragma unroll 4
    for (int k = 0; k < 128; k++) {
        u64 a2[4], bb[4];
#pragma unroll
        for (int i = 0; i < 4; i++)
            a2[i] = *(const u64*)(Xt + k * S130 + rbase + 2 * i);
#pragma unroll
        for (int j = 0; j < 4; j++) {
            float bv = Ws[(lane + 32 * j) * S129 + k];
            bb[j] = pk2(bv, bv);
        }
#pragma unroll
        for (int i = 0; i < 4; i++)
#pragma unroll
            for (int j = 0; j < 4; j++) fma2(acc[i][j], a2[i], bb[j]);
    }
#pragma unroll
    for (int i = 0; i < 4; i++)
#pragma unroll
        for (int j = 0; j < 4; j++) {
            float2 v = up2(acc[i][j]);
            size_t g = (size_t)(row0 + rbase + 2 * i) * 128 + lane + 32 * j;
            O[g] = v.x;
            O[g + 128] = v.y;
        }
}

// =====================================================================
// attention scores + head-avg softmax -> accP registers (R=2).
// Ut: k-major [128d][130p] (pre-scaled 0.25), Vt: k-major [128d][129q].
// =====================================================================
__device__ __forceinline__ void attn_scores(const float* __restrict__ Ut,
                                            const float* __restrict__ Vt,
                                            u64 accP[2][4], int lane, int rbase) {
#pragma unroll
    for (int i = 0; i < 2; i++)
#pragma unroll
        for (int j = 0; j < 4; j++) accP[i][j] = 0ull;

    for (int h = 0; h < 8; h++) {
        int ho = h * 16;
        u64 s2[2][4];
#pragma unroll
        for (int i = 0; i < 2; i++)
#pragma unroll
            for (int j = 0; j < 4; j++) s2[i][j] = 0ull;
#pragma unroll
        for (int r = 0; r < 16; r++) {
            int k = ho + r;
            u64 a2[2], bb[4];
#pragma unroll
            for (int i = 0; i < 2; i++)
                a2[i] = *(const u64*)(Ut + k * S130 + rbase + 2 * i);
#pragma unroll
            for (int j = 0; j < 4; j++) {
                float bv = Vt[k * S129 + lane + 32 * j];
                bb[j] = pk2(bv, bv);
            }
#pragma unroll
            for (int i = 0; i < 2; i++)
#pragma unroll
                for (int j = 0; j < 4; j++) fma2(s2[i][j], a2[i], bb[j]);
        }
#pragma unroll
        for (int i = 0; i < 2; i++) {
            float2 sv[4];
#pragma unroll
            for (int j = 0; j < 4; j++) sv[j] = up2(s2[i][j]);
            float mx0 = fmaxf(fmaxf(sv[0].x, sv[1].x), fmaxf(sv[2].x, sv[3].x));
            float mx1 = fmaxf(fmaxf(sv[0].y, sv[1].y), fmaxf(sv[2].y, sv[3].y));
#pragma unroll
            for (int o = 16; o > 0; o >>= 1) {
                mx0 = fmaxf(mx0, __shfl_xor_sync(0xffffffffu, mx0, o));
                mx1 = fmaxf(mx1, __shfl_xor_sync(0xffffffffu, mx1, o));
            }
            float e0[4], e1[4];
            float su0 = 0.f, su1 = 0.f;
#pragma unroll
            for (int j = 0; j < 4; j++) {
                e0[j] = __expf(sv[j].x - mx0);
                e1[j] = __expf(sv[j].y - mx1);
                su0 += e0[j]; su1 += e1[j];
            }
#pragma unroll
            for (int o = 16; o > 0; o >>= 1) {
                su0 += __shfl_xor_sync(0xffffffffu, su0, o);
                su1 += __shfl_xor_sync(0xffffffffu, su1, o);
            }
            float inv0 = __fdividef(1.0f, su0 * 16.0f);
            float inv1 = __fdividef(1.0f, su1 * 16.0f);
            u64 ip = pk2(inv0, inv1);
#pragma unroll
            for (int j = 0; j < 4; j++) fma2(accP[i][j], pk2(e0[j], e1[j]), ip);
        }
    }
}

// =====================================================================
// K3: time attention. block=(b,c), 1024 threads.
// =====================================================================
__global__ __launch_bounds__(1024) void k_time_attn() {
    extern __shared__ float sm[];
    float* R0 = sm;                   // Ut then At, 128*130
    float* R1 = sm + 128 * S130;      // Vt(129) then Qn(128)
    int tid = threadIdx.x, lane = tid & 31, w = tid >> 5;
    int rbase = w * 4;
    size_t base = (size_t)blockIdx.x * 16384;

    for (int i = tid; i < 16384; i += 1024) {
        int p = i >> 7, d = i & 127;
        R0[d * S130 + p] = 0.25f * g_tu[base + i];
        R1[d * S129 + p] = g_tv[base + i];
    }
    __syncthreads();

    u64 accP[2][4];
    attn_scores(R0, R1, accP, lane, rbase);
    __syncthreads();

#pragma unroll
    for (int i = 0; i < 2; i++)
#pragma unroll
        for (int j = 0; j < 4; j++)
            *(u64*)(R0 + (lane + 32 * j) * S130 + rbase + 2 * i) = accP[i][j];
    for (int i = tid; i < 16384; i += 1024) {
        int p = i >> 7, d = i & 127;
        R1[p * 128 + d] = g_qzn[base + i];
    }
    __syncthreads();

    u64 m[2][4];
#pragma unroll
    for (int i = 0; i < 2; i++)
#pragma unroll
        for (int j = 0; j < 4; j++) m[i][j] = 0ull;
#pragma unroll 4
    for (int q = 0; q < 128; q++) {
        u64 a2[2], bb[4];
#pragma unroll
        for (int i = 0; i < 2; i++)
            a2[i] = *(const u64*)(R0 + q * S130 + rbase + 2 * i);
#pragma unroll
        for (int j = 0; j < 4; j++) {
            float bv = R1[q * 128 + lane + 32 * j];
            bb[j] = pk2(bv, bv);
        }
#pragma unroll
        for (int i = 0; i < 2; i++)
#pragma unroll
            for (int j = 0; j < 4; j++) fma2(m[i][j], a2[i], bb[j]);
    }
#pragma unroll
    for (int i = 0; i < 2; i++)
#pragma unroll
        for (int j = 0; j < 4; j++) {
            float2 v = up2(m[i][j]);
            size_t g = base + (size_t)(rbase + 2 * i) * 128 + lane + 32 * j;
            g_xacc[g] += v.x;
            g_xacc[g + 128] += v.y;
        }
}

// =====================================================================
// K4: channel attention. block=(b,p), 1024 threads.
// =====================================================================
__global__ __launch_bounds__(1024) void k_chan_attn() {
    extern __shared__ float sm[];
    float* R0 = sm;
    float* R1 = sm + 128 * S130;
    int tid = threadIdx.x, lane = tid & 31, w = tid >> 5;
    int rbase = w * 4;
    int bp = blockIdx.x;
    int b = bp >> 7, p = bp & 127;
    size_t base = (size_t)b * 2097152 + (size_t)p * 128;

    for (int i = tid; i < 16384; i += 1024) {
        int c = i >> 7, d = i & 127;
        size_t g = base + (size_t)c * 16384 + d;
        R0[d * S130 + c] = 0.25f * g_cu[g];
        R1[d * S129 + c] = g_cv[g];
    }
    __syncthreads();

    u64 accP[2][4];
    attn_scores(R0, R1, accP, lane, rbase);
    __syncthreads();

#pragma unroll
    for (int i = 0; i < 2; i++)
#pragma unroll
        for (int j = 0; j < 4; j++)
            *(u64*)(R0 + (lane + 32 * j) * S130 + rbase + 2 * i) = accP[i][j];
    __syncthreads();

    for (int i = tid; i < 16384; i += 1024) {
        int c = i >> 7, d = i & 127;
        size_t g = base + (size_t)c * 16384 + d;
        g_xacc[g] += R0[d * S130 + c] * g_qzn[g];
    }
}

// =====================================================================
// K5: topic. 128 rows/block, 512 threads, 512 blocks.
// gemm1: two R=2 half-passes; gemm2: R=4 into persistent macc.
// =====================================================================
__global__ __launch_bounds__(512) void k_topic(const float* __restrict__ topic) {
    extern __shared__ float sm[];
    float* Qt = sm;                          // [128k][130r]
    float* Tn = Qt + 128 * S130;             // [128g][129d]
    float* St = Tn + 128 * S129;             // [128g][130r]
    float* rs = St + 128 * S130;             // [128]
    int tid = threadIdx.x, lane = tid & 31, w = tid >> 5;
    int rbase = w * 8;
    int row0 = blockIdx.x * 128;
    int b = row0 >> 14;
    const float* Tb = topic + (size_t)b * NG * 128;

    for (int i = tid; i < 16384; i += 512) {
        int r = i >> 7, k = i & 127;
        Qt[k * S130 + r] = g_qzn[(size_t)(row0 + r) * 128 + k];
    }
    if (tid < 128) rs[tid] = 0.0f;

    u64 macc[4][4];
#pragma unroll
    for (int i = 0; i < 4; i++)
#pragma unroll
        for (int j = 0; j < 4; j++) macc[i][j] = 0ull;

    for (int gc = 0; gc < 4; gc++) {
        __syncthreads();
        for (int i = tid; i < 16384; i += 512) {
            int g = i >> 7, d = i & 127;
            Tn[g * S129 + d] = Tb[(size_t)(gc * 128 + g) * 128 + d];
        }
        __syncthreads();

        // gemm1 in two half passes (keeps live regs low next to macc)
        for (int hp = 0; hp < 2; hp++) {
            int rb2 = rbase + hp * 4;
            u64 s2[2][4];
#pragma unroll
            for (int i = 0; i < 2; i++)
#pragma unroll
                for (int j = 0; j < 4; j++) s2[i][j] = 0ull;
#pragma unroll 4
            for (int k = 0; k < 128; k++) {
                u64 a2[2], bb[4];
#pragma unroll
                for (int i = 0; i < 2; i++)
                    a2[i] = *(const u64*)(Qt + k * S130 + rb2 + 2 * i);
#pragma unroll
                for (int j = 0; j < 4; j++) {
                    float bv = Tn[(lane + 32 * j) * S129 + k];
                    bb[j] = pk2(bv, bv);
                }
#pragma unroll
                for (int i = 0; i < 2; i++)
#pragma unroll
                    for (int j = 0; j < 4; j++) fma2(s2[i][j], a2[i], bb[j]);
            }
#pragma unroll
            for (int i = 0; i < 2; i++) {
                float2 v[4];
                float su0 = 0.f, su1 = 0.f;
#pragma unroll
                for (int j = 0; j < 4; j++) {
                    v[j] = up2(s2[i][j]);
                    v[j].x = fmaxf(v[j].x, 0.0f);
                    v[j].y = fmaxf(v[j].y, 0.0f);
                    su0 += v[j].x; su1 += v[j].y;
                }
#pragma unroll
                for (int o = 16; o > 0; o >>= 1) {
                    su0 += __shfl_xor_sync(0xffffffffu, su0, o);
                    su1 += __shfl_xor_sync(0xffffffffu, su1, o);
                }
                if (lane == 0) {
                    rs[rb2 + 2 * i] += su0;
                    rs[rb2 + 2 * i + 1] += su1;
                }
#pragma unroll
                for (int j = 0; j < 4; j++)
                    *(u64*)(St + (lane + 32 * j) * S130 + rb2 + 2 * i) = pk2(v[j].x, v[j].y);
            }
        }
        __syncthreads();

        // gemm2: M[r][d] += S[r][g] * T[g][d], R=4
#pragma unroll 4
        for (int g = 0; g < 128; g++) {
            u64 a2[4], bb[4];
#pragma unroll
            for (int i = 0; i < 4; i++)
                a2[i] = *(const u64*)(St + g * S130 + rbase + 2 * i);
#pragma unroll
            for (int j = 0; j < 4; j++) {
                float bv = Tn[g * S129 + lane + 32 * j];
                bb[j] = pk2(bv, bv);
            }
#pragma unroll
            for (int i = 0; i < 4; i++)
#pragma unroll
                for (int j = 0; j < 4; j++) fma2(macc[i][j], a2[i], bb[j]);
        }
    }
#pragma unroll
    for (int i = 0; i < 4; i++) {
        float idn0 = 0.5f / fmaxf(rs[rbase + 2 * i], 1e-6f);
        float idn1 = 0.5f / fmaxf(rs[rbase + 2 * i + 1], 1e-6f);
#pragma unroll
        for (int j = 0; j < 4; j++) {
            float2 v = up2(macc[i][j]);
            size_t g = (size_t)(row0 + rbase + 2 * i) * 128 + lane + 32 * j;
            g_xacc[g] += v.x * idn0;
            g_xacc[g + 128] += v.y * idn1;
        }
    }
}

// =====================================================================
// K6: out = x + gelu(LN(x)@w1^T+b1)@w2^T+b2. 128 rows/block, 512 thr, R=4.
// =====================================================================
__global__ __launch_bounds__(512) void k_mlp(
    const float* __restrict__ gamma, const float* __restrict__ beta,
    const float* __restrict__ w1, const float* __restrict__ b1,
    const float* __restrict__ w2, const float* __restrict__ b2,
    float* __restrict__ out) {
    extern __shared__ float sm[];
    float* W1n = sm;                        // 128 x 129
    float* W2n = W1n + 128 * S129;          // 128 x 129
    float* Ht  = W2n + 128 * S129;          // [128d][130r], aliased by Tt
    int tid = threadIdx.x, lane = tid & 31, w = tid >> 5;
    int rbase = w * 8;
    int row0 = blockIdx.x * 128;

    for (int i = tid; i < 16384; i += 512) {
        int r = i >> 7, c = i & 127;
        W1n[r * S129 + c] = w1[i];
        W2n[r * S129 + c] = w2[i];
    }
    float4 g4 = *(const float4*)(gamma + lane * 4);
    float4 b4 = *(const float4*)(beta + lane * 4);
#pragma unroll
    for (int it = 0; it < 8; it++) {
        int r = rbase + it;
        size_t gb = (size_t)(row0 + r) * 128 + lane * 4;
        float4 v = *(const float4*)(g_xacc + gb);
        float s = v.x + v.y + v.z + v.w;
        float ss = v.x * v.x + v.y * v.y + v.z * v.z + v.w * v.w;
#pragma unroll
        for (int o = 16; o > 0; o >>= 1) {
            s += __shfl_xor_sync(0xffffffffu, s, o);
            ss += __shfl_xor_sync(0xffffffffu, ss, o);
        }
        float m = s * (1.0f / 128.0f);
        float var = ss * (1.0f / 128.0f) - m * m;
        float inv = rsqrtf(var + 1e-5f);
        Ht[(lane * 4 + 0) * S130 + r] = (v.x - m) * inv * g4.x + b4.x;
        Ht[(lane * 4 + 1) * S130 + r] = (v.y - m) * inv * g4.y + b4.y;
        Ht[(lane * 4 + 2) * S130 + r] = (v.z - m) * inv * g4.z + b4.z;
        Ht[(lane * 4 + 3) * S130 + r] = (v.w - m) * inv * g4.w + b4.w;
    }
    __syncthreads();

    float bs1[4], bs2[4];
#pragma unroll
    for (int j = 0; j < 4; j++) {
        bs1[j] = b1[lane + 32 * j];
        bs2[j] = b2[lane + 32 * j];
    }

    // gemm1, R=4
    u64 acc[4][4];
#pragma unroll
    for (int i = 0; i < 4; i++)
#pragma unroll
        for (int j = 0; j < 4; j++) acc[i][j] = 0ull;
#pragma unroll 4
    for (int k = 0; k < 128; k++) {
        u64 a2[4], bb[4];
#pragma unroll
        for (int i = 0; i < 4; i++)
            a2[i] = *(const u64*)(Ht + k * S130 + rbase + 2 * i);
#pragma unroll
        for (int j = 0; j < 4; j++) {
            float bv = W1n[(lane + 32 * j) * S129 + k];
            bb[j] = pk2(bv, bv);
        }
#pragma unroll
        for (int i = 0; i < 4; i++)
#pragma unroll
            for (int j = 0; j < 4; j++) fma2(acc[i][j], a2[i], bb[j]);
    }
    __syncthreads();   // all reads of Ht done before overwriting with Tt

    // gelu -> Tt (aliases Ht), k-major [128o][130r]
#pragma unroll
    for (int i = 0; i < 4; i++)
#pragma unroll
        for (int j = 0; j < 4; j++) {
            float2 v = up2(acc[i][j]);
            float x0 = v.x + bs1[j], x1 = v.y + bs1[j];
            float gl0 = 0.5f * x0 * (1.0f + erff(x0 * 0.70710678118654752f));
            float gl1 = 0.5f * x1 * (1.0f + erff(x1 * 0.70710678118654752f));
            *(u64*)(Ht + (lane + 32 * j) * S130 + rbase + 2 * i) = pk2(gl0, gl1);
        }
    __syncthreads();

    // gemm2 -> out, R=4
    u64 acc2[4][4];
#pragma unroll
    for (int i = 0; i < 4; i++)
#pragma unroll
        for (int j = 0; j < 4; j++) acc2[i][j] = 0ull;
#pragma unroll 4
    for (int o = 0; o < 128; o++) {
        u64 a2[4], bb[4];
#pragma unroll
        for (int i = 0; i < 4; i++)
            a2[i] = *(const u64*)(Ht + o * S130 + rbase + 2 * i);
#pragma unroll
        for (int j = 0; j < 4; j++) {
            float bv = W2n[(lane + 32 * j) * S129 + o];
            bb[j] = pk2(bv, bv);
        }
#pragma unroll
        for (int i = 0; i < 4; i++)
#pragma unroll
            for (int j = 0; j < 4; j++) fma2(acc2[i][j], a2[i], bb[j]);
    }
#pragma unroll
    for (int i = 0; i < 4; i++)
#pragma unroll
        for (int j = 0; j < 4; j++) {
            float2 v = up2(acc2[i][j]);
            size_t g = (size_t)(row0 + rbase + 2 * i) * 128 + lane + 32 * j;
            out[g] = g_xacc[g] + v.x + bs2[j];
            out[g + 128] = g_xacc[g + 128] + v.y + bs2[j];
        }
}

// =====================================================================
// launch
// =====================================================================
extern "C" void kernel_launch(void* const* d_in, const int* in_sizes, int n_in,
                              void* d_out, int out_size) {
    const float* qz    = (const float*)d_in[0];
    const float* unary = (const float*)d_in[1];
    const float* tuw   = (const float*)d_in[2];
    const float* tvw   = (const float*)d_in[3];
    const float* cuw   = (const float*)d_in[4];
    const float* cvw   = (const float*)d_in[5];
    const float* topic = (const float*)d_in[6];
    const float* gamma = (const float*)d_in[7];
    const float* beta  = (const float*)d_in[8];
    const float* w1    = (const float*)d_in[9];
    const float* b1    = (const float*)d_in[10];
    const float* w2    = (const float*)d_in[11];
    const float* b2    = (const float*)d_in[12];
    float* out = (float*)d_out;

    const int SM2 = (128 * S130 + 128 * S129) * 4;                     // 132608
    const int SMA = (128 * S130 + 128 * S129) * 4;                     // 132608
    const int SM5 = (128 * S130 + 128 * S129 + 128 * S130 + 128) * 4;  // 199680
    const int SM6 = (128 * S129 * 2 + 128 * S130) * 4;                 // 198656

    cudaFuncSetAttribute(k_gemm4, cudaFuncAttributeMaxDynamicSharedMemorySize, SM2);
    cudaFuncSetAttribute(k_time_attn, cudaFuncAttributeMaxDynamicSharedMemorySize, SMA);
    cudaFuncSetAttribute(k_chan_attn, cudaFuncAttributeMaxDynamicSharedMemorySize, SMA);
    cudaFuncSetAttribute(k_topic, cudaFuncAttributeMaxDynamicSharedMemorySize, SM5);
    cudaFuncSetAttribute(k_mlp, cudaFuncAttributeMaxDynamicSharedMemorySize, SM6);

    k_ln_init<<<NROW / 8, 256>>>(qz, unary, gamma, beta);
    k_gemm4<<<dim3(NROW / 128, 4), 512, SM2>>>(tuw, tvw, cuw, cvw);
    k_time_attn<<<NB * NC, 1024, SMA>>>();
    k_chan_attn<<<NB * NP, 1024, SMA>>>();
    k_topic<<<NROW / 128, 512, SM5>>>(topic);
    k_mlp<<<NROW / 128, 512, SM6>>>(gamma, beta, w1, b1, w2, b2, out);
}

// round 7
// speedup vs baseline: 1.4238x; 1.4238x over previous
#include <cuda_runtime.h>
#include <cuda_bf16.h>
#include <stdint.h>
#include <math.h>

#define NB 4
#define NC 128
#define NP 128
#define ND 128
#define NG 512
#define NROW (NB * NC * NP)            // 65536
#define NELEM ((size_t)NROW * ND)      // 8388608

typedef unsigned long long u64;

#define S130 130
#define S129 129
#define SA 136                         // bf16 stride for mma tiles
#define TILE_U16 (128 * SA)            // 17408 uint16 per tile

// -------------------- scratch --------------------
__device__ float g_qzn[NELEM];
__device__ float g_xacc[NELEM];
__device__ float g_tu[NELEM];
__device__ float g_tv[NELEM];
__device__ float g_cu[NELEM];
__device__ float g_cv[NELEM];

// -------------------- packed f32x2 helpers (attention) --------------------
__device__ __forceinline__ u64 pk2(float lo, float hi) {
    u64 r; asm("mov.b64 %0, {%1,%2};" : "=l"(r) : "f"(lo), "f"(hi)); return r;
}
__device__ __forceinline__ float2 up2(u64 v) {
    float2 f; asm("mov.b64 {%0,%1}, %2;" : "=f"(f.x), "=f"(f.y) : "l"(v)); return f;
}
__device__ __forceinline__ void fma2(u64 &d, u64 a, u64 b) {
    asm("fma.rn.f32x2 %0, %1, %2, %0;" : "+l"(d) : "l"(a), "l"(b));
}

// -------------------- bf16 split + mma.sync helpers --------------------
__device__ __forceinline__ uint32_t pkbf(__nv_bfloat16 a, __nv_bfloat16 b) {
    return (uint32_t)__bfloat16_as_ushort(a) | ((uint32_t)__bfloat16_as_ushort(b) << 16);
}
__device__ __forceinline__ void split2(float x0, float x1, uint32_t &hi, uint32_t &lo) {
    __nv_bfloat16 h0 = __float2bfloat16(x0), h1 = __float2bfloat16(x1);
    hi = pkbf(h0, h1);
    lo = pkbf(__float2bfloat16(x0 - __bfloat162float(h0)),
              __float2bfloat16(x1 - __bfloat162float(h1)));
}

__device__ __forceinline__ void mma_bf16(float* c, const uint32_t* a, const uint32_t* b) {
    asm volatile(
        "mma.sync.aligned.m16n8k16.row.col.f32.bf16.bf16.f32 "
        "{%0,%1,%2,%3}, {%4,%5,%6,%7}, {%8,%9}, {%0,%1,%2,%3};"
        : "+f"(c[0]), "+f"(c[1]), "+f"(c[2]), "+f"(c[3])
        : "r"(a[0]), "r"(a[1]), "r"(a[2]), "r"(a[3]), "r"(b[0]), "r"(b[1]));
}

// A fragment: r = m-tile row + g, k = k-tile + 2t
__device__ __forceinline__ void lda(const uint16_t* A, int r, int k, uint32_t* f) {
    const uint16_t* p = A + r * SA + k;
    f[0] = *(const uint32_t*)p;
    f[1] = *(const uint32_t*)(p + 8 * SA);
    f[2] = *(const uint32_t*)(p + 8);
    f[3] = *(const uint32_t*)(p + 8 * SA + 8);
}
// B fragment: n = n-tile + g, k = k-tile + 2t
__device__ __forceinline__ void ldb(const uint16_t* B, int n, int k, uint32_t* f) {
    const uint16_t* p = B + n * SA + k;
    f[0] = *(const uint32_t*)p;
    f[1] = *(const uint32_t*)(p + 8);
}

// natural [128][128] fp32 -> hi/lo bf16 tiles (stride 136)
__device__ __forceinline__ void conv_nat(const float* __restrict__ src,
                                         uint16_t* Ah, uint16_t* Al,
                                         int tid, int nthr) {
    for (int i = tid; i < 128 * 64; i += nthr) {
        int r = i >> 6, c = (i & 63) * 2;
        float2 v = *(const float2*)(src + r * 128 + c);
        uint32_t hi, lo; split2(v.x, v.y, hi, lo);
        *(uint32_t*)(Ah + r * SA + c) = hi;
        *(uint32_t*)(Al + r * SA + c) = lo;
    }
}
// transposed: dst[d][g] = src[g][d]
__device__ __forceinline__ void conv_trans(const float* __restrict__ src,
                                           uint16_t* Bh, uint16_t* Bl,
                                           int tid, int nthr) {
    for (int i = tid; i < 128 * 64; i += nthr) {
        int d = i & 127, gp = (i >> 7) * 2;
        float x0 = src[gp * 128 + d];
        float x1 = src[(gp + 1) * 128 + d];
        uint32_t hi, lo; split2(x0, x1, hi, lo);
        *(uint32_t*)(Bh + d * SA + gp) = hi;
        *(uint32_t*)(Bl + d * SA + gp) = lo;
    }
}

// 3-term warp GEMM: acc += A(m MT*16 x 128) @ B(n NT*8 x 128)^T
template <int MT, int NT>
__device__ __forceinline__ void warp_gemm3(
    const uint16_t* Ah, const uint16_t* Al,
    const uint16_t* Bh, const uint16_t* Bl,
    int wm, int wn, int g, int t, float (&acc)[MT][NT][4]) {
#pragma unroll
    for (int kt = 0; kt < 8; kt++) {
        int k = kt * 16 + 2 * t;
        uint32_t bh[NT][2], bl[NT][2];
#pragma unroll
        for (int nt = 0; nt < NT; nt++) {
            int n = wn + nt * 8 + g;
            ldb(Bh, n, k, bh[nt]);
            ldb(Bl, n, k, bl[nt]);
        }
#pragma unroll
        for (int mt = 0; mt < MT; mt++) {
            uint32_t ah[4], al[4];
            int r = wm + mt * 16 + g;
            lda(Ah, r, k, ah);
            lda(Al, r, k, al);
#pragma unroll
            for (int nt = 0; nt < NT; nt++) {
                mma_bf16(acc[mt][nt], ah, bh[nt]);
                mma_bf16(acc[mt][nt], ah, bl[nt]);
                mma_bf16(acc[mt][nt], al, bh[nt]);
            }
        }
    }
}

// =====================================================================
// K1: qzn = LN(qz); xacc = 0.5*(qz + unary).  one warp per row.
// =====================================================================
__global__ __launch_bounds__(256) void k_ln_init(
    const float* __restrict__ qz, const float* __restrict__ unary,
    const float* __restrict__ gamma, const float* __restrict__ beta) {
    int row = blockIdx.x * 8 + (threadIdx.x >> 5);
    int lane = threadIdx.x & 31;
    size_t base = (size_t)row * 128 + lane * 4;
    float4 v = *(const float4*)(qz + base);
    float s = v.x + v.y + v.z + v.w;
    float ss = v.x * v.x + v.y * v.y + v.z * v.z + v.w * v.w;
#pragma unroll
    for (int o = 16; o > 0; o >>= 1) {
        s += __shfl_xor_sync(0xffffffffu, s, o);
        ss += __shfl_xor_sync(0xffffffffu, ss, o);
    }
    float m = s * (1.0f / 128.0f);
    float var = ss * (1.0f / 128.0f) - m * m;
    float inv = rsqrtf(var + 1e-5f);
    float4 u = *(const float4*)(unary + base);
    float4 g4 = *(const float4*)(gamma + lane * 4);
    float4 b4 = *(const float4*)(beta + lane * 4);
    float4 qn, xa;
    qn.x = (v.x - m) * inv * g4.x + b4.x;
    qn.y = (v.y - m) * inv * g4.y + b4.y;
    qn.z = (v.z - m) * inv * g4.z + b4.z;
    qn.w = (v.w - m) * inv * g4.w + b4.w;
    xa.x = 0.5f * (v.x + u.x);
    xa.y = 0.5f * (v.y + u.y);
    xa.z = 0.5f * (v.z + u.z);
    xa.w = 0.5f * (v.w + u.w);
    *(float4*)(g_qzn + base) = qn;
    *(float4*)(g_xacc + base) = xa;
}

// =====================================================================
// K2 (mma): 4 batched linears. 128 rows/block, 256 thr, grid (512,4).
// warp tile m64 x n32.
// =====================================================================
__global__ __launch_bounds__(256) void k_gemm4(
    const float* __restrict__ w0, const float* __restrict__ w1,
    const float* __restrict__ w2, const float* __restrict__ w3) {
    extern __shared__ uint16_t smu[];
    uint16_t* Ah = smu;
    uint16_t* Al = Ah + TILE_U16;
    uint16_t* Bh = Al + TILE_U16;
    uint16_t* Bl = Bh + TILE_U16;
    int tid = threadIdx.x, lane = tid & 31, w = tid >> 5;
    int g = lane >> 2, t = lane & 3;
    int row0 = blockIdx.x * 128;
    int b = row0 >> 14;
    int which = blockIdx.y;
    const float* W = (which == 0 ? w0 : which == 1 ? w1 : which == 2 ? w2 : w3)
                     + (size_t)b * 16384;
    float* O = (which == 0 ? g_tu : which == 1 ? g_tv : which == 2 ? g_cu : g_cv);

    conv_nat(g_qzn + (size_t)row0 * 128, Ah, Al, tid, 256);
    conv_nat(W, Bh, Bl, tid, 256);
    __syncthreads();

    int wm = (w & 1) * 64, wn = (w >> 1) * 32;
    float acc[4][4][4] = {};
    warp_gemm3<4, 4>(Ah, Al, Bh, Bl, wm, wn, g, t, acc);

#pragma unroll
    for (int mt = 0; mt < 4; mt++)
#pragma unroll
        for (int nt = 0; nt < 4; nt++) {
            int row = row0 + wm + mt * 16 + g;
            int col = wn + nt * 8 + 2 * t;
            float2 v0 = {acc[mt][nt][0], acc[mt][nt][1]};
            float2 v1 = {acc[mt][nt][2], acc[mt][nt][3]};
            *(float2*)(O + (size_t)row * 128 + col) = v0;
            *(float2*)(O + (size_t)(row + 8) * 128 + col) = v1;
        }
}

// =====================================================================
// attention scores + head-avg softmax -> accP registers (FFMA2, R=2).
// =====================================================================
__device__ __forceinline__ void attn_scores(const float* __restrict__ Ut,
                                            const float* __restrict__ Vt,
                                            u64 accP[2][4], int lane, int rbase) {
#pragma unroll
    for (int i = 0; i < 2; i++)
#pragma unroll
        for (int j = 0; j < 4; j++) accP[i][j] = 0ull;

    for (int h = 0; h < 8; h++) {
        int ho = h * 16;
        u64 s2[2][4];
#pragma unroll
        for (int i = 0; i < 2; i++)
#pragma unroll
            for (int j = 0; j < 4; j++) s2[i][j] = 0ull;
#pragma unroll
        for (int r = 0; r < 16; r++) {
            int k = ho + r;
            u64 a2[2], bb[4];
#pragma unroll
            for (int i = 0; i < 2; i++)
                a2[i] = *(const u64*)(Ut + k * S130 + rbase + 2 * i);
#pragma unroll
            for (int j = 0; j < 4; j++) {
                float bv = Vt[k * S129 + lane + 32 * j];
                bb[j] = pk2(bv, bv);
            }
#pragma unroll
            for (int i = 0; i < 2; i++)
#pragma unroll
                for (int j = 0; j < 4; j++) fma2(s2[i][j], a2[i], bb[j]);
        }
#pragma unroll
        for (int i = 0; i < 2; i++) {
            float2 sv[4];
#pragma unroll
            for (int j = 0; j < 4; j++) sv[j] = up2(s2[i][j]);
            float mx0 = fmaxf(fmaxf(sv[0].x, sv[1].x), fmaxf(sv[2].x, sv[3].x));
            float mx1 = fmaxf(fmaxf(sv[0].y, sv[1].y), fmaxf(sv[2].y, sv[3].y));
#pragma unroll
            for (int o = 16; o > 0; o >>= 1) {
                mx0 = fmaxf(mx0, __shfl_xor_sync(0xffffffffu, mx0, o));
                mx1 = fmaxf(mx1, __shfl_xor_sync(0xffffffffu, mx1, o));
            }
            float e0[4], e1[4];
            float su0 = 0.f, su1 = 0.f;
#pragma unroll
            for (int j = 0; j < 4; j++) {
                e0[j] = __expf(sv[j].x - mx0);
                e1[j] = __expf(sv[j].y - mx1);
                su0 += e0[j]; su1 += e1[j];
            }
#pragma unroll
            for (int o = 16; o > 0; o >>= 1) {
                su0 += __shfl_xor_sync(0xffffffffu, su0, o);
                su1 += __shfl_xor_sync(0xffffffffu, su1, o);
            }
            float inv0 = __fdividef(1.0f, su0 * 16.0f);
            float inv1 = __fdividef(1.0f, su1 * 16.0f);
            u64 ip = pk2(inv0, inv1);
#pragma unroll
            for (int j = 0; j < 4; j++) fma2(accP[i][j], pk2(e0[j], e1[j]), ip);
        }
    }
}

// =====================================================================
// K3: time attention (FFMA2). block=(b,c), 1024 threads.
// =====================================================================
__global__ __launch_bounds__(1024) void k_time_attn() {
    extern __shared__ float sm[];
    float* R0 = sm;                   // Ut then At, 128*130
    float* R1 = sm + 128 * S130;      // Vt(129) then Qn(128)
    int tid = threadIdx.x, lane = tid & 31, w = tid >> 5;
    int rbase = w * 4;
    size_t base = (size_t)blockIdx.x * 16384;

    for (int i = tid; i < 16384; i += 1024) {
        int p = i >> 7, d = i & 127;
        R0[d * S130 + p] = 0.25f * g_tu[base + i];
        R1[d * S129 + p] = g_tv[base + i];
    }
    __syncthreads();

    u64 accP[2][4];
    attn_scores(R0, R1, accP, lane, rbase);
    __syncthreads();

#pragma unroll
    for (int i = 0; i < 2; i++)
#pragma unroll
        for (int j = 0; j < 4; j++)
            *(u64*)(R0 + (lane + 32 * j) * S130 + rbase + 2 * i) = accP[i][j];
    for (int i = tid; i < 16384; i += 1024) {
        int p = i >> 7, d = i & 127;
        R1[p * 128 + d] = g_qzn[base + i];
    }
    __syncthreads();

    u64 m[2][4];
#pragma unroll
    for (int i = 0; i < 2; i++)
#pragma unroll
        for (int j = 0; j < 4; j++) m[i][j] = 0ull;
#pragma unroll 4
    for (int q = 0; q < 128; q++) {
        u64 a2[2], bb[4];
#pragma unroll
        for (int i = 0; i < 2; i++)
            a2[i] = *(const u64*)(R0 + q * S130 + rbase + 2 * i);
#pragma unroll
        for (int j = 0; j < 4; j++) {
            float bv = R1[q * 128 + lane + 32 * j];
            bb[j] = pk2(bv, bv);
        }
#pragma unroll
        for (int i = 0; i < 2; i++)
#pragma unroll
            for (int j = 0; j < 4; j++) fma2(m[i][j], a2[i], bb[j]);
    }
#pragma unroll
    for (int i = 0; i < 2; i++)
#pragma unroll
        for (int j = 0; j < 4; j++) {
            float2 v = up2(m[i][j]);
            size_t g = base + (size_t)(rbase + 2 * i) * 128 + lane + 32 * j;
            g_xacc[g] += v.x;
            g_xacc[g + 128] += v.y;
        }
}

// =====================================================================
// K4: channel attention (FFMA2). block=(b,p), 1024 threads.
// =====================================================================
__global__ __launch_bounds__(1024) void k_chan_attn() {
    extern __shared__ float sm[];
    float* R0 = sm;
    float* R1 = sm + 128 * S130;
    int tid = threadIdx.x, lane = tid & 31, w = tid >> 5;
    int rbase = w * 4;
    int bp = blockIdx.x;
    int b = bp >> 7, p = bp & 127;
    size_t base = (size_t)b * 2097152 + (size_t)p * 128;

    for (int i = tid; i < 16384; i += 1024) {
        int c = i >> 7, d = i & 127;
        size_t g = base + (size_t)c * 16384 + d;
        R0[d * S130 + c] = 0.25f * g_cu[g];
        R1[d * S129 + c] = g_cv[g];
    }
    __syncthreads();

    u64 accP[2][4];
    attn_scores(R0, R1, accP, lane, rbase);
    __syncthreads();

#pragma unroll
    for (int i = 0; i < 2; i++)
#pragma unroll
        for (int j = 0; j < 4; j++)
            *(u64*)(R0 + (lane + 32 * j) * S130 + rbase + 2 * i) = accP[i][j];
    __syncthreads();

    for (int i = tid; i < 16384; i += 1024) {
        int c = i >> 7, d = i & 127;
        size_t g = base + (size_t)c * 16384 + d;
        g_xacc[g] += R0[d * S130 + c] * g_qzn[g];
    }
}

// =====================================================================
// K5 (mma): topic. 128 rows/block, 512 thr (16 warps, m32 x n32), 512 blk.
// =====================================================================
__global__ __launch_bounds__(512) void k_topic(const float* __restrict__ topic) {
    extern __shared__ uint16_t smu[];
    uint16_t* Qh = smu;
    uint16_t* Ql = Qh + TILE_U16;
    uint16_t* Bh = Ql + TILE_U16;
    uint16_t* Bl = Bh + TILE_U16;
    uint16_t* Sh = Bl + TILE_U16;
    uint16_t* Sl = Sh + TILE_U16;
    float* rs = (float*)(Sl + TILE_U16);   // [128]
    int tid = threadIdx.x, lane = tid & 31, w = tid >> 5;
    int g = lane >> 2, t = lane & 3;
    int wm = (w >> 2) * 32, wn = (w & 3) * 32;
    int row0 = blockIdx.x * 128;
    int b = row0 >> 14;
    const float* Tg = topic + (size_t)b * NG * 128;

    conv_nat(g_qzn + (size_t)row0 * 128, Qh, Ql, tid, 512);
    if (tid < 128) rs[tid] = 0.0f;

    float macc[2][4][4] = {};

    for (int gc = 0; gc < 4; gc++) {
        const float* Tc = Tg + (size_t)(gc * 128) * 128;
        __syncthreads();                 // prev gemm2 done reading B/S
        conv_nat(Tc, Bh, Bl, tid, 512);  // B = T natural [g][d]
        __syncthreads();

        // gemm1: S = Q @ T^T
        float sacc[2][4][4] = {};
        warp_gemm3<2, 4>(Qh, Ql, Bh, Bl, wm, wn, g, t, sacc);
        __syncthreads();                 // all done reading B before overwrite

        // relu + row sums + split S to smem
#pragma unroll
        for (int mt = 0; mt < 2; mt++) {
            int row = wm + mt * 16 + g;
            float p0 = 0.f, p1 = 0.f;
#pragma unroll
            for (int nt = 0; nt < 4; nt++) {
                float r0 = fmaxf(sacc[mt][nt][0], 0.f);
                float r1 = fmaxf(sacc[mt][nt][1], 0.f);
                float r2 = fmaxf(sacc[mt][nt][2], 0.f);
                float r3 = fmaxf(sacc[mt][nt][3], 0.f);
                p0 += r0 + r1;
                p1 += r2 + r3;
                int col = wn + nt * 8 + 2 * t;
                uint32_t hi, lo;
                split2(r0, r1, hi, lo);
                *(uint32_t*)(Sh + row * SA + col) = hi;
                *(uint32_t*)(Sl + row * SA + col) = lo;
                split2(r2, r3, hi, lo);
                *(uint32_t*)(Sh + (row + 8) * SA + col) = hi;
                *(uint32_t*)(Sl + (row + 8) * SA + col) = lo;
            }
            p0 += __shfl_xor_sync(0xffffffffu, p0, 1);
            p0 += __shfl_xor_sync(0xffffffffu, p0, 2);
            p1 += __shfl_xor_sync(0xffffffffu, p1, 1);
            p1 += __shfl_xor_sync(0xffffffffu, p1, 2);
            if (t == 0) {
                atomicAdd(rs + row, p0);
                atomicAdd(rs + row + 8, p1);
            }
        }
        conv_trans(Tc, Bh, Bl, tid, 512);  // B = T^T: [d][g]
        __syncthreads();

        // gemm2: M += S @ T
        warp_gemm3<2, 4>(Sh, Sl, Bh, Bl, wm, wn, g, t, macc);
    }
    __syncthreads();

#pragma unroll
    for (int mt = 0; mt < 2; mt++) {
        int row = wm + mt * 16 + g;
        float idn0 = 0.5f / fmaxf(rs[row], 1e-6f);
        float idn1 = 0.5f / fmaxf(rs[row + 8], 1e-6f);
#pragma unroll
        for (int nt = 0; nt < 4; nt++) {
            int col = wn + nt * 8 + 2 * t;
            size_t g0 = (size_t)(row0 + row) * 128 + col;
            size_t g1 = (size_t)(row0 + row + 8) * 128 + col;
            float2 x0 = *(float2*)(g_xacc + g0);
            float2 x1 = *(float2*)(g_xacc + g1);
            x0.x += macc[mt][nt][0] * idn0;
            x0.y += macc[mt][nt][1] * idn0;
            x1.x += macc[mt][nt][2] * idn1;
            x1.y += macc[mt][nt][3] * idn1;
            *(float2*)(g_xacc + g0) = x0;
            *(float2*)(g_xacc + g1) = x1;
        }
    }
}

// =====================================================================
// K6 (mma): out = x + gelu(LN(x)@w1^T+b1)@w2^T+b2. 128 rows, 256 thr.
// =====================================================================
__global__ __launch_bounds__(256) void k_mlp(
    const float* __restrict__ gamma, const float* __restrict__ beta,
    const float* __restrict__ w1, const float* __restrict__ b1,
    const float* __restrict__ w2, const float* __restrict__ b2,
    float* __restrict__ out) {
    extern __shared__ uint16_t smu[];
    uint16_t* Ah = smu;                 // H (then gelu(H@W1))
    uint16_t* Al = Ah + TILE_U16;
    uint16_t* Bh = Al + TILE_U16;       // W1 then W2
    uint16_t* Bl = Bh + TILE_U16;
    int tid = threadIdx.x, lane = tid & 31, w = tid >> 5;
    int g = lane >> 2, t = lane & 3;
    int row0 = blockIdx.x * 128;
    int wm = (w & 1) * 64, wn = (w >> 1) * 32;

    // LN of xacc -> split into Ah/Al. warp w: rows w*16..w*16+15.
    float4 g4 = *(const float4*)(gamma + lane * 4);
    float4 b4 = *(const float4*)(beta + lane * 4);
#pragma unroll
    for (int it = 0; it < 16; it++) {
        int r = w * 16 + it;
        size_t gb = (size_t)(row0 + r) * 128 + lane * 4;
        float4 v = *(const float4*)(g_xacc + gb);
        float s = v.x + v.y + v.z + v.w;
        float ss = v.x * v.x + v.y * v.y + v.z * v.z + v.w * v.w;
#pragma unroll
        for (int o = 16; o > 0; o >>= 1) {
            s += __shfl_xor_sync(0xffffffffu, s, o);
            ss += __shfl_xor_sync(0xffffffffu, ss, o);
        }
        float m = s * (1.0f / 128.0f);
        float var = ss * (1.0f / 128.0f) - m * m;
        float inv = rsqrtf(var + 1e-5f);
        float q0 = (v.x - m) * inv * g4.x + b4.x;
        float q1 = (v.y - m) * inv * g4.y + b4.y;
        float q2 = (v.z - m) * inv * g4.z + b4.z;
        float q3 = (v.w - m) * inv * g4.w + b4.w;
        uint32_t hi, lo;
        split2(q0, q1, hi, lo);
        *(uint32_t*)(Ah + r * SA + lane * 4) = hi;
        *(uint32_t*)(Al + r * SA + lane * 4) = lo;
        split2(q2, q3, hi, lo);
        *(uint32_t*)(Ah + r * SA + lane * 4 + 2) = hi;
        *(uint32_t*)(Al + r * SA + lane * 4 + 2) = lo;
    }
    conv_nat(w1, Bh, Bl, tid, 256);
    __syncthreads();

    // gemm1: H @ W1^T
    float acc[4][4][4] = {};
    warp_gemm3<4, 4>(Ah, Al, Bh, Bl, wm, wn, g, t, acc);
    __syncthreads();   // all reads of Ah/Bh done

    // gelu(+b1) -> overwrite Ah/Al; convert W2 -> Bh/Bl
#pragma unroll
    for (int mt = 0; mt < 4; mt++)
#pragma unroll
        for (int nt = 0; nt < 4; nt++) {
            int row = wm + mt * 16 + g;
            int col = wn + nt * 8 + 2 * t;
            float bb0 = b1[col], bb1 = b1[col + 1];
            float x0 = acc[mt][nt][0] + bb0, x1 = acc[mt][nt][1] + bb1;
            float x2 = acc[mt][nt][2] + bb0, x3 = acc[mt][nt][3] + bb1;
            float gl0 = 0.5f * x0 * (1.0f + erff(x0 * 0.70710678118654752f));
            float gl1 = 0.5f * x1 * (1.0f + erff(x1 * 0.70710678118654752f));
            float gl2 = 0.5f * x2 * (1.0f + erff(x2 * 0.70710678118654752f));
            float gl3 = 0.5f * x3 * (1.0f + erff(x3 * 0.70710678118654752f));
            uint32_t hi, lo;
            split2(gl0, gl1, hi, lo);
            *(uint32_t*)(Ah + row * SA + col) = hi;
            *(uint32_t*)(Al + row * SA + col) = lo;
            split2(gl2, gl3, hi, lo);
            *(uint32_t*)(Ah + (row + 8) * SA + col) = hi;
            *(uint32_t*)(Al + (row + 8) * SA + col) = lo;
        }
    conv_nat(w2, Bh, Bl, tid, 256);
    __syncthreads();

    // gemm2 -> out
    float acc2[4][4][4] = {};
    warp_gemm3<4, 4>(Ah, Al, Bh, Bl, wm, wn, g, t, acc2);

#pragma unroll
    for (int mt = 0; mt < 4; mt++)
#pragma unroll
        for (int nt = 0; nt < 4; nt++) {
            int row = row0 + wm + mt * 16 + g;
            int col = wn + nt * 8 + 2 * t;
            float bb0 = b2[col], bb1 = b2[col + 1];
            size_t g0 = (size_t)row * 128 + col;
            size_t g1 = (size_t)(row + 8) * 128 + col;
            float2 x0 = *(const float2*)(g_xacc + g0);
            float2 x1 = *(const float2*)(g_xacc + g1);
            float2 o0 = {x0.x + acc2[mt][nt][0] + bb0, x0.y + acc2[mt][nt][1] + bb1};
            float2 o1 = {x1.x + acc2[mt][nt][2] + bb0, x1.y + acc2[mt][nt][3] + bb1};
            *(float2*)(out + g0) = o0;
            *(float2*)(out + g1) = o1;
        }
}

// =====================================================================
// launch
// =====================================================================
extern "C" void kernel_launch(void* const* d_in, const int* in_sizes, int n_in,
                              void* d_out, int out_size) {
    const float* qz    = (const float*)d_in[0];
    const float* unary = (const float*)d_in[1];
    const float* tuw   = (const float*)d_in[2];
    const float* tvw   = (const float*)d_in[3];
    const float* cuw   = (const float*)d_in[4];
    const float* cvw   = (const float*)d_in[5];
    const float* topic = (const float*)d_in[6];
    const float* gamma = (const float*)d_in[7];
    const float* beta  = (const float*)d_in[8];
    const float* w1    = (const float*)d_in[9];
    const float* b1    = (const float*)d_in[10];
    const float* w2    = (const float*)d_in[11];
    const float* b2    = (const float*)d_in[12];
    float* out = (float*)d_out;

    const int SMG = 4 * TILE_U16 * 2;                   // 139264
    const int SMT = 6 * TILE_U16 * 2 + 512;             // 209408
    const int SMA = (128 * S130 + 128 * S129) * 4;      // 132608

    cudaFuncSetAttribute(k_gemm4, cudaFuncAttributeMaxDynamicSharedMemorySize, SMG);
    cudaFuncSetAttribute(k_time_attn, cudaFuncAttributeMaxDynamicSharedMemorySize, SMA);
    cudaFuncSetAttribute(k_chan_attn, cudaFuncAttributeMaxDynamicSharedMemorySize, SMA);
    cudaFuncSetAttribute(k_topic, cudaFuncAttributeMaxDynamicSharedMemorySize, SMT);
    cudaFuncSetAttribute(k_mlp, cudaFuncAttributeMaxDynamicSharedMemorySize, SMG);

    k_ln_init<<<NROW / 8, 256>>>(qz, unary, gamma, beta);
    k_gemm4<<<dim3(NROW / 128, 4), 256, SMG>>>(tuw, tvw, cuw, cvw);
    k_time_attn<<<NB * NC, 1024, SMA>>>();
    k_chan_attn<<<NB * NP, 1024, SMA>>>();
    k_topic<<<NROW / 128, 512, SMT>>>(topic);
    k_mlp<<<NROW / 128, 256, SMG>>>(gamma, beta, w1, b1, w2, b2, out);
}